// round 5
// baseline (speedup 1.0000x reference)
#include <cuda_runtime.h>
#include <cuda_bf16.h>
#include <cstdint>

typedef unsigned long long u64;

// ---------------- static scratch ----------------
// activations layout: (p, b, c) : act[(p*128 + b)*256 + c]
__device__ __align__(16) float g_bufA[512 * 128 * 256];   // 67 MB
__device__ __align__(16) float g_bufB[256 * 128 * 256];   // 33.5 MB
__device__ __align__(16) float g_part[4194304];           // 16.8 MB split-K partials

// ---------------- helpers ----------------
__device__ __forceinline__ uint32_t s2u(const void* p) {
    uint32_t a;
    asm("{\n\t.reg .u64 t;\n\tcvta.to.shared.u64 t, %1;\n\tcvt.u32.u64 %0, t;\n\t}" : "=r"(a) : "l"(p));
    return a;
}
__device__ __forceinline__ uint32_t packbf(float lo, float hi) {
    uint32_t r;
    asm("cvt.rn.bf16x2.f32 %0, %1, %2;" : "=r"(r) : "f"(hi), "f"(lo));
    return r;
}
__device__ __forceinline__ void split2(float x0, float x1, uint32_t& hi, uint32_t& lo) {
    uint32_t h = packbf(x0, x1);
    __nv_bfloat162 h2 = *(__nv_bfloat162*)&h;
    float r0 = x0 - __bfloat162float(h2.x);
    float r1 = x1 - __bfloat162float(h2.y);
    lo = packbf(r0, r1);
    hi = h;
}
__device__ __forceinline__ void ldsm4(uint32_t* r, uint32_t addr) {
    asm volatile("ldmatrix.sync.aligned.m8n8.x4.shared.b16 {%0,%1,%2,%3}, [%4];"
        : "=r"(r[0]), "=r"(r[1]), "=r"(r[2]), "=r"(r[3]) : "r"(addr));
}
__device__ __forceinline__ void mma16816(float* d, const uint32_t* a, uint32_t b0, uint32_t b1) {
    asm volatile("mma.sync.aligned.m16n8k16.row.col.f32.bf16.bf16.f32 "
        "{%0,%1,%2,%3}, {%4,%5,%6,%7}, {%8,%9}, {%0,%1,%2,%3};"
        : "+f"(d[0]), "+f"(d[1]), "+f"(d[2]), "+f"(d[3])
        : "r"(a[0]), "r"(a[1]), "r"(a[2]), "r"(a[3]), "r"(b0), "r"(b1));
}

// ---------------- layer 0 ----------------
__global__ void layer0_kernel(const float* __restrict__ x, const float* __restrict__ w0,
                              float* __restrict__ out)
{
    __shared__ float xs[6][128];
    const int d   = blockIdx.x;
    const int tid = threadIdx.x;
#pragma unroll
    for (int i = 0; i < 3; i++) {
        int e = tid + i * 256;
        int ck = e >> 7, b = e & 127;
        int c = ck >> 1, k = ck & 1;
        xs[ck][b] = x[(b * 3 + c) * 1024 + 2 * d + k];
    }
    __syncthreads();
    const int b  = tid & 127;
    const int oh = tid >> 7;
    const float2* w2 = (const float2*)w0;
    for (int o = oh; o < 256; o += 2) {
        float acc = 0.f;
#pragma unroll
        for (int c = 0; c < 3; c++) {
            float2 wv = w2[(o * 3 + c) * 512 + d];
            acc += xs[c * 2 + 0][b] * wv.x + xs[c * 2 + 1][b] * wv.y;
        }
        out[((size_t)d * 128 + b) * 256 + o] = fmaxf(acc * 0.5773502691896258f, 0.f);
    }
}

// ---------------- layers 1..9: warp-mma bf16x3, 512 threads / 16 warps ----------------
// CTA: M=128(b) x N=128(o half) x K-slice (nst*32 kappa), kappa = 2c+k
// smem stage: A,B tiles 128 rows x 128B (bytes 0-63 = 32 hi bf16, 64-127 = lo), SW128
#define SMEM_BYTES 65536

__global__ __launch_bounds__(512, 1)
void lc_mma(const float* __restrict__ in, const float* __restrict__ w,
            float* __restrict__ out, int dl, int nst, float scale, int partial)
{
    extern __shared__ __align__(1024) char smem[];
    const uint32_t sb = s2u(smem);
    const int tid  = threadIdx.x;
    const int wid  = tid >> 5, lane = tid & 31;
    const int oh   = blockIdx.x;
    const int d    = blockIdx.y;
    const int s    = blockIdx.z;
    const int cbase = s * nst * 16;

    // ---- loader roles: 512 threads, row r (0..127) x channel-quarter q (0..3) ----
    const int r = tid >> 2;
    const int q = tid & 3;
    const float*  a0p = in + ((size_t)(2 * d) * 128 + r) * 256;
    const float*  a1p = a0p + 128 * 256;
    const float2* w2  = (const float2*)w;
    const size_t  wrow = (size_t)(oh * 128 + r) * 256;

    const uint32_t rowb = (uint32_t)r * 128, xs_ = (uint32_t)(r & 7) << 4;
    const uint32_t offH = rowb + (((uint32_t)q * 16) ^ xs_);
    const uint32_t offL = rowb + ((((uint32_t)q + 4) * 16) ^ xs_);

    const uint32_t AB[2] = { sb, sb + 32768 };   // stage buffers; B at +16384

    // ---- compute roles: 4x4 warp grid, warp tile 32x32 ----
    const int mw = wid & 3, nw = wid >> 2;
    const uint32_t co = (uint32_t)(lane >> 4) * 16;
    const uint32_t xa = (uint32_t)(lane & 7) << 4;
    uint32_t rA[2], rB[2];
#pragma unroll
    for (int mi = 0; mi < 2; mi++) rA[mi] = (uint32_t)(mw * 32 + mi * 16 + (lane & 15)) * 128;
#pragma unroll
    for (int bj = 0; bj < 2; bj++) rB[bj] = (uint32_t)(nw * 32 + bj * 16 + (lane & 15)) * 128;

    float D[2][4][4];
#pragma unroll
    for (int i = 0; i < 2; i++)
#pragma unroll
        for (int j = 0; j < 4; j++)
#pragma unroll
            for (int k = 0; k < 4; k++) D[i][j][k] = 0.f;

    // 2-deep register staging
    float4 sa0[2], sa1[2];
    float2 sfb[2][4];

    auto issue_loads = [&](int t, int slot) {
        const int c0 = cbase + t * 16 + 4 * q;
        sa0[slot] = *(const float4*)(a0p + c0);
        sa1[slot] = *(const float4*)(a1p + c0);
#pragma unroll
        for (int j = 0; j < 4; j++)
            sfb[slot][j] = w2[(wrow + (size_t)(c0 + j)) * dl + d];
    };

    auto convert_store = [&](int slot, int buf) {
        uint32_t Ah[4], Al[4], Bh[4], Bl[4];
        const float* a0 = (const float*)&sa0[slot];
        const float* a1 = (const float*)&sa1[slot];
#pragma unroll
        for (int j = 0; j < 4; j++) {
            split2(a0[j], a1[j], Ah[j], Al[j]);
            split2(sfb[slot][j].x, sfb[slot][j].y, Bh[j], Bl[j]);
        }
        const uint32_t ab = AB[buf], bb = AB[buf] + 16384;
        asm volatile("st.shared.v4.b32 [%0], {%1,%2,%3,%4};" :: "r"(ab + offH), "r"(Ah[0]), "r"(Ah[1]), "r"(Ah[2]), "r"(Ah[3]));
        asm volatile("st.shared.v4.b32 [%0], {%1,%2,%3,%4};" :: "r"(ab + offL), "r"(Al[0]), "r"(Al[1]), "r"(Al[2]), "r"(Al[3]));
        asm volatile("st.shared.v4.b32 [%0], {%1,%2,%3,%4};" :: "r"(bb + offH), "r"(Bh[0]), "r"(Bh[1]), "r"(Bh[2]), "r"(Bh[3]));
        asm volatile("st.shared.v4.b32 [%0], {%1,%2,%3,%4};" :: "r"(bb + offL), "r"(Bl[0]), "r"(Bl[1]), "r"(Bl[2]), "r"(Bl[3]));
    };

    issue_loads(0, 0);
    if (nst > 1) issue_loads(1, 1);
    convert_store(0, 0);
    __syncthreads();

    for (int t = 0; t < nst; t++) {
        const int buf = t & 1;
        if (t + 2 < nst) issue_loads(t + 2, t & 1);

        const uint32_t ab = AB[buf], bb = AB[buf] + 16384;
#pragma unroll
        for (int kk = 0; kk < 2; kk++) {
            uint32_t Ahf[2][4], Alf[2][4], Bhf[2][4], Blf[2][4];
            const uint32_t khi = (uint32_t)(32 * kk) + co;
            const uint32_t klo = khi + 64;
#pragma unroll
            for (int mi = 0; mi < 2; mi++) {
                ldsm4(Ahf[mi], ab + rA[mi] + (khi ^ xa));
                ldsm4(Alf[mi], ab + rA[mi] + (klo ^ xa));
            }
#pragma unroll
            for (int bj = 0; bj < 2; bj++) {
                ldsm4(Bhf[bj], bb + rB[bj] + (khi ^ xa));
                ldsm4(Blf[bj], bb + rB[bj] + (klo ^ xa));
            }
#pragma unroll
            for (int mi = 0; mi < 2; mi++) {
#pragma unroll
                for (int nj = 0; nj < 4; nj++) {
                    const int bt = nj >> 1, bs = nj & 1;
                    mma16816(D[mi][nj], Ahf[mi], Bhf[bt][bs], Bhf[bt][bs + 2]);
                    mma16816(D[mi][nj], Alf[mi], Bhf[bt][bs], Bhf[bt][bs + 2]);
                    mma16816(D[mi][nj], Ahf[mi], Blf[bt][bs], Blf[bt][bs + 2]);
                }
            }
        }

        if (t + 1 < nst) convert_store((t + 1) & 1, buf ^ 1);
        __syncthreads();
    }

    // ---- epilogue ----
    const int colq = nw * 32 + 2 * (lane & 3);
    if (partial) {
        float* pp = g_part + ((size_t)(s * 2 + oh) * dl + d) * 16384;
#pragma unroll
        for (int mi = 0; mi < 2; mi++) {
            const int b0 = mw * 32 + mi * 16 + (lane >> 2);
#pragma unroll
            for (int nj = 0; nj < 4; nj++) {
                const int col = colq + nj * 8;
                *(float2*)(pp + (size_t)b0 * 128 + col)       = make_float2(D[mi][nj][0], D[mi][nj][1]);
                *(float2*)(pp + (size_t)(b0 + 8) * 128 + col) = make_float2(D[mi][nj][2], D[mi][nj][3]);
            }
        }
    } else {
        float* op = out + (size_t)d * 128 * 256 + oh * 128;
#pragma unroll
        for (int mi = 0; mi < 2; mi++) {
            const int b0 = mw * 32 + mi * 16 + (lane >> 2);
#pragma unroll
            for (int nj = 0; nj < 4; nj++) {
                const int col = colq + nj * 8;
                float2 v0 = make_float2(fmaxf(D[mi][nj][0] * scale, 0.f), fmaxf(D[mi][nj][1] * scale, 0.f));
                float2 v1 = make_float2(fmaxf(D[mi][nj][2] * scale, 0.f), fmaxf(D[mi][nj][3] * scale, 0.f));
                *(float2*)(op + (size_t)b0 * 256 + col)       = v0;
                *(float2*)(op + (size_t)(b0 + 8) * 256 + col) = v1;
            }
        }
    }
}

// ---------------- split-K reduce + relu ----------------
__global__ void reduce_relu_kernel(const float* __restrict__ part, float* __restrict__ out,
                                   int n, int dl, int S, float scale)
{
    int idx = blockIdx.x * 256 + threadIdx.x;
    if (idx >= n) return;
    const int o  = idx & 255;
    const int b  = (idx >> 8) & 127;
    const int dd = idx >> 15;
    const int ohh = o >> 7, ol = o & 127;
    float sum = 0.f;
    for (int si = 0; si < S; si++)
        sum += part[((size_t)(si * 2 + ohh) * dl + dd) * 16384 + b * 128 + ol];
    out[idx] = fmaxf(sum * scale, 0.f);
}

// ---------------- head ----------------
__global__ void head_kernel(const float* __restrict__ act, const float* __restrict__ beta,
                            float* __restrict__ out)
{
    const int t = blockIdx.x;
    const int b = threadIdx.x;
    float s = 0.f;
#pragma unroll 8
    for (int o = 0; o < 256; o++)
        s += act[b * 256 + o] * __ldg(&beta[o * 10 + t]);
    out[b * 10 + t] = s * (1.0f / 256.0f);
}

// ---------------- launch ----------------
extern "C" void kernel_launch(void* const* d_in, const int* in_sizes, int n_in,
                              void* d_out, int out_size)
{
    const float* x = (const float*)d_in[0];
    const float* wl[10];
    for (int l = 0; l < 10; l++) wl[l] = (const float*)d_in[1 + l];
    const float* beta = (const float*)d_in[11];
    float* out = (float*)d_out;

    float *bufA, *bufB, *part;
    cudaGetSymbolAddress((void**)&bufA, g_bufA);
    cudaGetSymbolAddress((void**)&bufB, g_bufB);
    cudaGetSymbolAddress((void**)&part, g_part);

    cudaFuncSetAttribute(lc_mma, cudaFuncAttributeMaxDynamicSharedMemorySize, SMEM_BYTES);

    layer0_kernel<<<512, 256>>>(x, wl[0], bufA);

    float* cur = bufA;
    float* nxt = bufB;
    int dl = 256;
    const float scale = 0.0625f;
    for (int l = 1; l <= 9; l++) {
        int S;
        if (dl >= 128)      S = 1;
        else if (dl == 64)  S = 2;
        else if (dl == 32)  S = 4;
        else if (dl >= 8)   S = 8;
        else                S = 16;
        const int nst = 16 / S;
        if (S == 1) {
            lc_mma<<<dim3(2, dl, 1), 512, SMEM_BYTES>>>(cur, wl[l], nxt, dl, nst, scale, 0);
        } else {
            lc_mma<<<dim3(2, dl, S), 512, SMEM_BYTES>>>(cur, wl[l], part, dl, nst, scale, 1);
            const int n = dl * 32768;
            reduce_relu_kernel<<<(n + 255) / 256, 256>>>(part, nxt, n, dl, S, scale);
        }
        float* tmp = cur; cur = nxt; nxt = tmp;
        dl >>= 1;
    }

    head_kernel<<<10, 128>>>(cur, beta, out);
}